// round 4
// baseline (speedup 1.0000x reference)
#include <cuda_runtime.h>
#include <math.h>

#define BB 16
#define CC 384
#define HH 96
#define WW 96
#define HW (HH*WW)
#define CAND 2048
#define ANCH 512
#define KK2 49
#define TAU_INV 10.0f

// ---------------- scratch (device globals; no allocation anywhere) ----------------
__device__ float g_tn[(size_t)BB*HW*CC];      // teacher, normalized, channels-last [b][y][x][c]
__device__ float g_sn[(size_t)BB*HW*CC];      // student,  normalized, channels-last
__device__ float g_sims[(size_t)BB*CAND*KK2]; // teacher sims (already /TAU)
__device__ float g_ent[BB*CAND];
__device__ int   g_sel[BB*ANCH];
__device__ float g_loss;

// ---------------- k0: zero the loss accumulator ----------------
__global__ void k_zero() { g_loss = 0.0f; }

// ---------------- k1: fused per-pixel L2-normalize + transpose to channels-last ----
// DST=0 -> g_tn (teacher), DST=1 -> g_sn (student). Destination resolved on
// device, so kernel_launch never touches symbol addresses.
#define PIX 16
template <int DST>
__global__ void __launch_bounds__(256) k_norm_transpose(const float* __restrict__ in) {
    __shared__ float tile[CC][PIX + 1];
    __shared__ float ssum[16][PIX];
    __shared__ float rinv[PIX];
    int blk  = blockIdx.x;
    int b    = blk / (HW / PIX);
    int pix0 = (blk % (HW / PIX)) * PIX;
    int t    = threadIdx.x;
    int p    = t & (PIX - 1);
    int cr   = t >> 4;                       // 0..15
    const float* src = in + (size_t)b * CC * HW + pix0;
    float acc = 0.0f;
#pragma unroll
    for (int i = 0; i < CC / 16; i++) {      // 24 iters, coalesced 64B per 16 lanes
        int c = i * 16 + cr;
        float v = src[(size_t)c * HW + p];
        tile[c][p] = v;
        acc += v * v;
    }
    ssum[cr][p] = acc;
    __syncthreads();
    if (cr == 0) {
        float s = 0.0f;
#pragma unroll
        for (int r = 0; r < 16; r++) s += ssum[r][p];
        rinv[p] = 1.0f / fmaxf(sqrtf(s), 1e-12f);
    }
    __syncthreads();
    int lane = t & 31, w = t >> 5;           // 8 warps
    float* gout = (DST == 0) ? g_tn : g_sn;
    float* dst = gout + ((size_t)b * HW + pix0) * CC;
#pragma unroll
    for (int j = 0; j < PIX / 8; j++) {      // 2
        int pp = w * (PIX / 8) + j;
        float r = rinv[pp];
#pragma unroll
        for (int i2 = 0; i2 < CC / 32; i2++) {  // 12, fully coalesced 128B stores
            int c = lane + 32 * i2;
            dst[(size_t)pp * CC + c] = tile[c][pp] * r;
        }
    }
}

// ---------------- warp-level window-sims helper ----------------
// Each lane holds 12 channels (3 float4) of the center vector; for each of the
// 49 neighbors it accumulates a partial dot, then butterfly-reduces so every
// lane ends with the full (scaled) sim vector.
__device__ __forceinline__ void warp_window_sims(const float* __restrict__ feat,
                                                 int b, int y, int x, int lane,
                                                 float s[KK2]) {
    const float4* base = (const float4*)(feat + (size_t)b * HW * CC);
    const float4* cp = base + (size_t)(y * WW + x) * (CC / 4);
    float4 c0 = cp[lane], c1 = cp[lane + 32], c2 = cp[lane + 64];
#pragma unroll
    for (int ky = 0; ky < 7; ky++) {
#pragma unroll
        for (int kx = 0; kx < 7; kx++) {
            const float4* np = base + (size_t)((y + ky - 3) * WW + (x + kx - 3)) * (CC / 4);
            float4 n0 = np[lane], n1 = np[lane + 32], n2 = np[lane + 64];
            float d = c0.x * n0.x + c0.y * n0.y + c0.z * n0.z + c0.w * n0.w;
            d += c1.x * n1.x + c1.y * n1.y + c1.z * n1.z + c1.w * n1.w;
            d += c2.x * n2.x + c2.y * n2.y + c2.z * n2.z + c2.w * n2.w;
            s[ky * 7 + kx] = d;
        }
    }
#pragma unroll
    for (int k = 0; k < KK2; k++) {
        float v = s[k];
#pragma unroll
        for (int o = 16; o > 0; o >>= 1) v += __shfl_xor_sync(0xffffffffu, v, o);
        s[k] = v * TAU_INV;
    }
}

// ---------------- k2: candidate sims (stored) + entropy ----------------
__global__ void __launch_bounds__(256) k_cand(const int* __restrict__ anchors) {
    int gw   = (blockIdx.x * blockDim.x + threadIdx.x) >> 5;
    int lane = threadIdx.x & 31;
    if (gw >= BB * CAND) return;
    int b = gw >> 11;            // / CAND
    int m = gw & (CAND - 1);
    int y = anchors[2 * m], x = anchors[2 * m + 1];

    float s[KK2];
    warp_window_sims(g_tn, b, y, x, lane, s);

    // cooperative store of the sims row (all lanes hold identical s)
    float* srow = g_sims + (size_t)gw * KK2;
    if (lane < KK2) srow[lane] = s[lane];
    if (lane + 32 < KK2) srow[lane + 32] = s[lane + 32];

    // entropy of softmax(s), redundant per lane
    float mx = s[0];
#pragma unroll
    for (int k = 1; k < KK2; k++) mx = fmaxf(mx, s[k]);
    float sum = 0.0f;
#pragma unroll
    for (int k = 0; k < KK2; k++) { s[k] = expf(s[k] - mx); sum += s[k]; }
    float inv = 1.0f / sum;
    float e = 0.0f;
#pragma unroll
    for (int k = 0; k < KK2; k++) {
        float pk = s[k] * inv;
        e -= pk * logf(pk + 1e-6f);
    }
    if (lane == 0) g_ent[gw] = e;
}

// ---------------- k3: exact top-512 (smallest entropy) per batch via bitonic sort --
__global__ void __launch_bounds__(1024) k_topk() {
    __shared__ float v[CAND];
    __shared__ int   idx[CAND];
    int b = blockIdx.x;
    int t = threadIdx.x;   // 1024
    v[t]          = g_ent[b * CAND + t];
    v[t + 1024]   = g_ent[b * CAND + t + 1024];
    idx[t]        = t;
    idx[t + 1024] = t + 1024;
    __syncthreads();
    for (int kk = 2; kk <= CAND; kk <<= 1) {
        for (int j = kk >> 1; j > 0; j >>= 1) {
            int i  = ((t & ~(j - 1)) << 1) | (t & (j - 1));
            int p2 = i | j;
            bool up = ((i & kk) == 0);
            float vi = v[i], vp = v[p2];
            if ((vi > vp) == up) {
                v[i] = vp; v[p2] = vi;
                int ti = idx[i]; idx[i] = idx[p2]; idx[p2] = ti;
            }
            __syncthreads();
        }
    }
    if (t < ANCH) g_sel[b * ANCH + t] = idx[t];   // ascending entropy -> smallest 512
}

// ---------------- k4: KL divergence over selected anchors ----------------
__global__ void __launch_bounds__(256) k_kl(const int* __restrict__ anchors) {
    int gw   = (blockIdx.x * blockDim.x + threadIdx.x) >> 5;
    int lane = threadIdx.x & 31;
    if (gw >= BB * ANCH) return;
    int b = gw >> 9;             // / ANCH
    int m = g_sel[gw];
    int y = anchors[2 * m], x = anchors[2 * m + 1];

    float ss[KK2];
    warp_window_sims(g_sn, b, y, x, lane, ss);

    const float* trow = g_sims + (size_t)(b * CAND + m) * KK2;
    float st[KK2];
#pragma unroll
    for (int k = 0; k < KK2; k++) st[k] = trow[k];   // uniform broadcast loads

    float mxs = ss[0], mxt = st[0];
#pragma unroll
    for (int k = 1; k < KK2; k++) { mxs = fmaxf(mxs, ss[k]); mxt = fmaxf(mxt, st[k]); }
    float sums = 0.0f, sumt = 0.0f;
#pragma unroll
    for (int k = 0; k < KK2; k++) { sums += expf(ss[k] - mxs); sumt += expf(st[k] - mxt); }
    float ls = logf(sums), lt = logf(sumt);
    float kl = 0.0f;
#pragma unroll
    for (int k = 0; k < KK2; k++) {
        float lpt = st[k] - mxt - lt;
        float lps = ss[k] - mxs - ls;
        kl += expf(lpt) * (lpt - lps);
    }
    if (lane == 0) atomicAdd(&g_loss, kl);
}

// ---------------- k5: finalize ----------------
__global__ void k_final(float* __restrict__ out) {
    out[0] = g_loss / (float)(BB * ANCH);
}

// ---------------- launch: kernel launches ONLY (graph-capture safe) ----------------
extern "C" void kernel_launch(void* const* d_in, const int* in_sizes, int n_in,
                              void* d_out, int out_size) {
    const float* student = (const float*)d_in[0];
    const float* teacher = (const float*)d_in[1];
    const int*   anchors = (const int*)d_in[2];
    float* out = (float*)d_out;

    k_zero<<<1, 1>>>();

    int nt_blocks = BB * HW / PIX;                  // 9216
    k_norm_transpose<0><<<nt_blocks, 256>>>(teacher);   // -> g_tn
    k_norm_transpose<1><<<nt_blocks, 256>>>(student);   // -> g_sn

    int cand_blocks = BB * CAND / 8;                // 4096 blocks, 8 warps each
    k_cand<<<cand_blocks, 256>>>(anchors);

    k_topk<<<BB, 1024>>>();

    int kl_blocks = BB * ANCH / 8;                  // 1024 blocks
    k_kl<<<kl_blocks, 256>>>(anchors);

    k_final<<<1, 1>>>(out);
}